// round 3
// baseline (speedup 1.0000x reference)
#include <cuda_runtime.h>
#include <cstdint>
#include <cstddef>

// Problem constants
#define T_STEPS 256
#define BB      64
#define DD      1024
#define ND3     3072   // 3*DD

// ---------------------------------------------------------------------------
// Device scratch (allocation-free rule: __device__ globals)
// ---------------------------------------------------------------------------
__device__ float    g_xproj[(size_t)T_STEPS * BB * ND3]; // [T*B, 3D] = 201 MB
__device__ float    g_WhT[(size_t)3 * DD * DD];          // W_h transposed: [n=3D][k=D]
__device__ unsigned g_bar;                               // grid barrier counter
__device__ int      g_dones_is_byte;                     // 1 if dones is 1-byte bool

// ---------------------------------------------------------------------------
// Packed f32x2 helpers (Blackwell: fma.rn.f32x2, 2x scalar FFMA throughput)
// ---------------------------------------------------------------------------
__device__ __forceinline__ unsigned long long pk2(float lo, float hi) {
    unsigned long long r;
    asm("mov.b64 %0, {%1, %2};" : "=l"(r) : "f"(lo), "f"(hi));
    return r;
}
__device__ __forceinline__ void fma2(unsigned long long& d,
                                     unsigned long long a, unsigned long long b) {
    asm("fma.rn.f32x2 %0, %1, %2, %0;" : "+l"(d) : "l"(a), "l"(b));
}
__device__ __forceinline__ float2 up2(unsigned long long v) {
    float2 f;
    asm("mov.b64 {%0, %1}, %2;" : "=f"(f.x), "=f"(f.y) : "l"(v));
    return f;
}
__device__ __forceinline__ float sigmoidf_(float x) {
    return 1.0f / (1.0f + __expf(-x));
}

// ---------------------------------------------------------------------------
// Kernel -1: probe dones dtype. Reads the first T*B bytes as u32 words.
// int32 bools -> every word in {0,1}. Packed byte bools -> (w.h.p.) some
// word > 1 (any set bool in bytes 1..3 of a word). Deterministic.
// ---------------------------------------------------------------------------
__global__ void probe_dones(const unsigned* __restrict__ d) {
    __shared__ int any_big;
    if (threadIdx.x == 0) any_big = 0;
    __syncthreads();
    const int nwords = (T_STEPS * BB) / 4;   // 4096 words = 16384 bytes (safe either way)
    int local = 0;
    for (int i = threadIdx.x; i < nwords; i += blockDim.x)
        if (d[i] > 1u) local = 1;
    if (local) any_big = 1;
    __syncthreads();
    if (threadIdx.x == 0) {
        g_dones_is_byte = any_big;
        g_bar = 0u;                           // reset grid barrier for this replay
    }
}

// ---------------------------------------------------------------------------
// Kernel 0: transpose W_h [D, 3D] -> g_WhT [3D, D]
// ---------------------------------------------------------------------------
__global__ void transpose_wh(const float* __restrict__ W) {
    __shared__ float tile[32][33];
    int n  = blockIdx.x * 32 + threadIdx.x;   // column in W (0..3071)
    int k0 = blockIdx.y * 32;
#pragma unroll
    for (int i = threadIdx.y; i < 32; i += 8)
        tile[i][threadIdx.x] = W[(size_t)(k0 + i) * ND3 + n];
    __syncthreads();
    int k  = k0 + threadIdx.x;
    int n0 = blockIdx.x * 32;
#pragma unroll
    for (int i = threadIdx.y; i < 32; i += 8)
        g_WhT[(size_t)(n0 + i) * DD + k] = tile[threadIdx.x][i];
}

// ---------------------------------------------------------------------------
// Kernel 1: x_proj = ins @ W_i + b_i   (M=16384, N=3072, K=1024)
// 128x128 tile, BK=16, 256 threads, 8x8 per thread, f32x2-packed along N.
// ---------------------------------------------------------------------------
__global__ void __launch_bounds__(256, 1) gemm_xproj(
    const float* __restrict__ A,   // ins  [16384, 1024]
    const float* __restrict__ Bw,  // W_i  [1024, 3072]
    const float* __restrict__ bias)
{
    __shared__ __align__(16) float As[16][132];  // transposed A tile, padded
    __shared__ __align__(16) float Bs[16][128];

    const int tid = threadIdx.x;
    const int tx = tid & 15, ty = tid >> 4;
    const int m0 = blockIdx.y << 7, n0 = blockIdx.x << 7;

    unsigned long long acc[8][4];
#pragma unroll
    for (int i = 0; i < 8; i++)
#pragma unroll
        for (int q = 0; q < 4; q++) acc[i][q] = 0ull;

    for (int k0 = 0; k0 < DD; k0 += 16) {
        // A tile: 128 rows x 16 k, store transposed As[k][m]
#pragma unroll
        for (int i = 0; i < 2; i++) {
            int e = tid + (i << 8);             // 0..511 float4 slots
            int row = e >> 2, c = e & 3;
            float4 v = *(const float4*)(A + (size_t)(m0 + row) * DD + k0 + c * 4);
            As[c * 4 + 0][row] = v.x;
            As[c * 4 + 1][row] = v.y;
            As[c * 4 + 2][row] = v.z;
            As[c * 4 + 3][row] = v.w;
        }
        // B tile: 16 k x 128 n
#pragma unroll
        for (int i = 0; i < 2; i++) {
            int e = tid + (i << 8);
            int kr = e >> 5, nc = e & 31;
            float4 v = *(const float4*)(Bw + (size_t)(k0 + kr) * ND3 + n0 + nc * 4);
            *(float4*)&Bs[kr][nc * 4] = v;
        }
        __syncthreads();
#pragma unroll
        for (int kk = 0; kk < 16; kk++) {
            float4 a0 = *(const float4*)&As[kk][ty * 4];
            float4 a1 = *(const float4*)&As[kk][64 + ty * 4];
            ulonglong2 b0 = *(const ulonglong2*)&Bs[kk][tx * 4];
            ulonglong2 b1 = *(const ulonglong2*)&Bs[kk][64 + tx * 4];
            float a[8] = {a0.x, a0.y, a0.z, a0.w, a1.x, a1.y, a1.z, a1.w};
#pragma unroll
            for (int i = 0; i < 8; i++) {
                unsigned long long ap = pk2(a[i], a[i]);
                fma2(acc[i][0], ap, b0.x);
                fma2(acc[i][1], ap, b0.y);
                fma2(acc[i][2], ap, b1.x);
                fma2(acc[i][3], ap, b1.y);
            }
        }
        __syncthreads();
    }
    // epilogue: + bias, store
#pragma unroll
    for (int i = 0; i < 8; i++) {
        int r = m0 + ((i < 4) ? (ty * 4 + i) : (64 + ty * 4 + i - 4));
#pragma unroll
        for (int q = 0; q < 4; q++) {
            int cb = n0 + ((q < 2) ? (tx * 4 + q * 2) : (64 + tx * 4 + (q - 2) * 2));
            float2 v = up2(acc[i][q]);
            g_xproj[(size_t)r * ND3 + cb]     = v.x + bias[cb];
            g_xproj[(size_t)r * ND3 + cb + 1] = v.y + bias[cb + 1];
        }
    }
}

// ---------------------------------------------------------------------------
// Kernel 2: persistent scan. 128 CTAs x 256 threads (all co-resident).
// CTA c owns columns j in [8c, 8c+8); warp w -> column j = 8c+w; lane owns
// batch rows (lane, lane+32). h source for step t is ys[t-1] (or init/hiddens
// per done flag). Grid-wide software barrier between steps.
// ---------------------------------------------------------------------------
__global__ void __launch_bounds__(256, 1) scan_kernel(
    const float* __restrict__ hiddens,      // [T, B, D]
    const void* __restrict__ dones_raw,     // [T, B] bool (int32 OR byte; probed)
    const float* __restrict__ init_carry,   // [B, D]
    const float* __restrict__ b_hn,         // [D]
    float* __restrict__ out)                // [B*D final | T*B*D ys]
{
    __shared__ __align__(16) float hs[64][132];
    __shared__ unsigned char s_done[64];

    const int tid  = threadIdx.x;
    const int lane = tid & 31;
    const int w    = tid >> 5;
    const int j    = (blockIdx.x << 3) + w;  // 0..1023
    const int b0   = lane, b1 = lane + 32;
    float* ys = out + (size_t)BB * DD;       // ys region

    const int is_byte = g_dones_is_byte;
    const unsigned char* dones_b = (const unsigned char*)dones_raw;
    const int*           dones_i = (const int*)dones_raw;

    const int jchunk = j >> 7, joff = j & 127;
    const float* Wr = g_WhT + ((size_t)j << 10);
    const float* Wz = g_WhT + ((size_t)(DD + j) << 10);
    const float* Wn = g_WhT + ((size_t)(2 * DD + j) << 10);
    const float bhn = b_hn[j];
    const unsigned G = gridDim.x;

    for (int t = 0; t < T_STEPS; t++) {
        if (tid < 64) {
            s_done[tid] = is_byte ? dones_b[t * 64 + tid]
                                  : (unsigned char)(dones_i[t * 64 + tid] != 0);
        }
        const float* prevb = (t == 0) ? init_carry : (ys + (size_t)(t - 1) * (BB * DD));
        const float* hidt  = hiddens + (size_t)t * (BB * DD);

        unsigned long long ar0 = 0, ar1 = 0, az0 = 0, az1 = 0, an0 = 0, an1 = 0;
        unsigned long long br0 = 0, br1 = 0, bz0 = 0, bz1 = 0, bn0 = 0, bn1 = 0;
        float hself0 = 0.f, hself1 = 0.f;

        for (int kc = 0; kc < 8; kc++) {
            __syncthreads();
            const int k0 = kc << 7;
            // cooperative load of done-masked h chunk [64][128] (bypass L1: cross-CTA data)
#pragma unroll
            for (int i = 0; i < 8; i++) {
                int e = tid + (i << 8);
                int b = e >> 5;
                int kk = (e & 31) << 2;
                const float* src = s_done[b] ? (hidt + ((size_t)b << 10))
                                             : (prevb + ((size_t)b << 10));
                float4 v = __ldcv((const float4*)(src + k0 + kk));
                *(float4*)&hs[b][kk] = v;
            }
            __syncthreads();
            if (kc == jchunk) { hself0 = hs[b0][joff]; hself1 = hs[b1][joff]; }

            const float* wr = Wr + k0;
            const float* wz = Wz + k0;
            const float* wn = Wn + k0;
#pragma unroll 8
            for (int kk = 0; kk < 128; kk += 4) {
                ulonglong2 h0 = *(const ulonglong2*)&hs[b0][kk];
                ulonglong2 h1 = *(const ulonglong2*)&hs[b1][kk];
                ulonglong2 wrv = *(const ulonglong2*)(wr + kk);
                ulonglong2 wzv = *(const ulonglong2*)(wz + kk);
                ulonglong2 wnv = *(const ulonglong2*)(wn + kk);
                fma2(ar0, h0.x, wrv.x); fma2(br0, h0.y, wrv.y);
                fma2(ar1, h1.x, wrv.x); fma2(br1, h1.y, wrv.y);
                fma2(az0, h0.x, wzv.x); fma2(bz0, h0.y, wzv.y);
                fma2(az1, h1.x, wzv.x); fma2(bz1, h1.y, wzv.y);
                fma2(an0, h0.x, wnv.x); fma2(bn0, h0.y, wnv.y);
                fma2(an1, h1.x, wnv.x); fma2(bn1, h1.y, wnv.y);
            }
        }
        // reduce packed accumulators
        float2 p;
        p = up2(ar0); float sr0 = p.x + p.y; p = up2(br0); sr0 += p.x + p.y;
        p = up2(ar1); float sr1 = p.x + p.y; p = up2(br1); sr1 += p.x + p.y;
        p = up2(az0); float sz0 = p.x + p.y; p = up2(bz0); sz0 += p.x + p.y;
        p = up2(az1); float sz1 = p.x + p.y; p = up2(bz1); sz1 += p.x + p.y;
        p = up2(an0); float sn0 = p.x + p.y; p = up2(bn0); sn0 += p.x + p.y;
        p = up2(an1); float sn1 = p.x + p.y; p = up2(bn1); sn1 += p.x + p.y;

        size_t base0 = ((size_t)t * 64 + b0) * ND3 + j;
        size_t base1 = ((size_t)t * 64 + b1) * ND3 + j;
        float xr0 = g_xproj[base0], xz0 = g_xproj[base0 + DD], xn0 = g_xproj[base0 + 2 * DD];
        float xr1 = g_xproj[base1], xz1 = g_xproj[base1 + DD], xn1 = g_xproj[base1 + 2 * DD];

        float r0 = sigmoidf_(xr0 + sr0);
        float z0 = sigmoidf_(xz0 + sz0);
        float nn0 = tanhf(xn0 + r0 * (sn0 + bhn));
        float h0n = (1.0f - z0) * nn0 + z0 * hself0;

        float r1 = sigmoidf_(xr1 + sr1);
        float z1 = sigmoidf_(xz1 + sz1);
        float nn1 = tanhf(xn1 + r1 * (sn1 + bhn));
        float h1n = (1.0f - z1) * nn1 + z1 * hself1;

        ys[((size_t)t * 64 + b0) * DD + j] = h0n;
        ys[((size_t)t * 64 + b1) * DD + j] = h1n;
        if (t == T_STEPS - 1) {
            out[(size_t)b0 * DD + j] = h0n;   // final_carry == ys[T-1]
            out[(size_t)b1 * DD + j] = h1n;
        }

        // grid-wide barrier (monotonic counter; reset by probe kernel each launch)
        __syncthreads();
        if (tid == 0) {
            __threadfence();
            atomicAdd(&g_bar, 1u);
            unsigned target = (unsigned)(t + 1) * G;
            while (*(volatile unsigned*)&g_bar < target) { }
            __threadfence();
        }
        __syncthreads();
    }
}

// ---------------------------------------------------------------------------
// Launch
// ---------------------------------------------------------------------------
extern "C" void kernel_launch(void* const* d_in, const int* in_sizes, int n_in,
                              void* d_out, int out_size) {
    (void)in_sizes; (void)n_in; (void)out_size;
    const float* ins        = (const float*)d_in[0];
    const float* hiddens    = (const float*)d_in[1];
    const void*  dones      = d_in[2];
    const float* init_carry = (const float*)d_in[3];
    const float* W_i        = (const float*)d_in[4];
    const float* W_h        = (const float*)d_in[5];
    const float* b_i        = (const float*)d_in[6];
    const float* b_hn       = (const float*)d_in[7];
    float* out = (float*)d_out;

    probe_dones<<<1, 256>>>((const unsigned*)dones);
    transpose_wh<<<dim3(ND3 / 32, DD / 32), dim3(32, 8)>>>(W_h);
    gemm_xproj<<<dim3(ND3 / 128, (T_STEPS * BB) / 128), 256>>>(ins, W_i, b_i);
    scan_kernel<<<128, 256>>>(hiddens, dones, init_carry, b_hn, out);
}

// round 4
// speedup vs baseline: 1.7567x; 1.7567x over previous
#include <cuda_runtime.h>
#include <cstdint>
#include <cstddef>

#define T_STEPS 256
#define BB      64
#define DD      1024
#define ND3     3072
#define TBTOT   (T_STEPS * BB)   // 16384

typedef unsigned long long ull;

// ---------------------------------------------------------------------------
// Device scratch
// ---------------------------------------------------------------------------
__device__ float    g_xproj [(size_t)TBTOT * ND3];   // [tb][n]  201MB
__device__ float    g_xprojT[(size_t)ND3 * TBTOT];   // [n][tb]  201MB
__device__ float    g_WhT  [(size_t)ND3 * DD];       // [n][k]
__device__ unsigned g_bar;
__device__ int      g_dones_is_byte;

// ---------------------------------------------------------------------------
// f32x2 helpers
// ---------------------------------------------------------------------------
__device__ __forceinline__ ull pk2(float lo, float hi) {
    ull r; asm("mov.b64 %0, {%1, %2};" : "=l"(r) : "f"(lo), "f"(hi)); return r;
}
__device__ __forceinline__ void fma2(ull& d, ull a, ull b) {
    asm("fma.rn.f32x2 %0, %1, %2, %0;" : "+l"(d) : "l"(a), "l"(b));
}
__device__ __forceinline__ float2 up2(ull v) {
    float2 f; asm("mov.b64 {%0, %1}, %2;" : "=f"(f.x), "=f"(f.y) : "l"(v)); return f;
}
__device__ __forceinline__ float sigmoidf_(float x) { return 1.0f / (1.0f + __expf(-x)); }

// ---------------------------------------------------------------------------
// probe dones dtype (int32 bool vs byte bool) + reset grid barrier
// ---------------------------------------------------------------------------
__global__ void probe_dones(const unsigned* __restrict__ d) {
    __shared__ int any_big;
    if (threadIdx.x == 0) any_big = 0;
    __syncthreads();
    const int nwords = (T_STEPS * BB) / 4;
    int local = 0;
    for (int i = threadIdx.x; i < nwords; i += blockDim.x)
        if (d[i] > 1u) local = 1;
    if (local) any_big = 1;
    __syncthreads();
    if (threadIdx.x == 0) { g_dones_is_byte = any_big; g_bar = 0u; }
}

// ---------------------------------------------------------------------------
// transpose W_h [D,3D] -> g_WhT [3D,D]
// ---------------------------------------------------------------------------
__global__ void transpose_wh(const float* __restrict__ W) {
    __shared__ float tile[32][33];
    int n  = blockIdx.x * 32 + threadIdx.x;
    int k0 = blockIdx.y * 32;
#pragma unroll
    for (int i = threadIdx.y; i < 32; i += 8)
        tile[i][threadIdx.x] = W[(size_t)(k0 + i) * ND3 + n];
    __syncthreads();
    int k  = k0 + threadIdx.x;
    int n0 = blockIdx.x * 32;
#pragma unroll
    for (int i = threadIdx.y; i < 32; i += 8)
        g_WhT[(size_t)(n0 + i) * DD + k] = tile[threadIdx.x][i];
}

// ---------------------------------------------------------------------------
// transpose g_xproj [16384,3072] -> g_xprojT [3072,16384]
// ---------------------------------------------------------------------------
__global__ void transpose_xproj() {
    __shared__ float tile[32][33];
    int n  = blockIdx.x * 32 + threadIdx.x;   // 0..3071
    int r0 = blockIdx.y * 32;                 // 0..16383
#pragma unroll
    for (int i = threadIdx.y; i < 32; i += 8)
        tile[i][threadIdx.x] = g_xproj[(size_t)(r0 + i) * ND3 + n];
    __syncthreads();
    int r  = r0 + threadIdx.x;
    int n0 = blockIdx.x * 32;
#pragma unroll
    for (int i = threadIdx.y; i < 32; i += 8)
        g_xprojT[(size_t)(n0 + i) * TBTOT + r] = tile[threadIdx.x][i];
}

// ---------------------------------------------------------------------------
// x_proj = ins @ W_i + b_i  (M=16384, N=3072, K=1024); 2 CTAs/SM
// ---------------------------------------------------------------------------
__global__ void __launch_bounds__(256, 2) gemm_xproj(
    const float* __restrict__ A, const float* __restrict__ Bw,
    const float* __restrict__ bias)
{
    __shared__ __align__(16) float As[16][132];
    __shared__ __align__(16) float Bs[16][128];

    const int tid = threadIdx.x;
    const int tx = tid & 15, ty = tid >> 4;
    const int m0 = blockIdx.y << 7, n0 = blockIdx.x << 7;

    ull acc[8][4];
#pragma unroll
    for (int i = 0; i < 8; i++)
#pragma unroll
        for (int q = 0; q < 4; q++) acc[i][q] = 0ull;

    for (int k0 = 0; k0 < DD; k0 += 16) {
#pragma unroll
        for (int i = 0; i < 2; i++) {
            int e = tid + (i << 8);
            int row = e >> 2, c = e & 3;
            float4 v = *(const float4*)(A + (size_t)(m0 + row) * DD + k0 + c * 4);
            As[c * 4 + 0][row] = v.x; As[c * 4 + 1][row] = v.y;
            As[c * 4 + 2][row] = v.z; As[c * 4 + 3][row] = v.w;
        }
#pragma unroll
        for (int i = 0; i < 2; i++) {
            int e = tid + (i << 8);
            int kr = e >> 5, nc = e & 31;
            float4 v = *(const float4*)(Bw + (size_t)(k0 + kr) * ND3 + n0 + nc * 4);
            *(float4*)&Bs[kr][nc * 4] = v;
        }
        __syncthreads();
#pragma unroll
        for (int kk = 0; kk < 16; kk++) {
            float4 a0 = *(const float4*)&As[kk][ty * 4];
            float4 a1 = *(const float4*)&As[kk][64 + ty * 4];
            ulonglong2 b0 = *(const ulonglong2*)&Bs[kk][tx * 4];
            ulonglong2 b1 = *(const ulonglong2*)&Bs[kk][64 + tx * 4];
            float a[8] = {a0.x, a0.y, a0.z, a0.w, a1.x, a1.y, a1.z, a1.w};
#pragma unroll
            for (int i = 0; i < 8; i++) {
                ull ap = pk2(a[i], a[i]);
                fma2(acc[i][0], ap, b0.x); fma2(acc[i][1], ap, b0.y);
                fma2(acc[i][2], ap, b1.x); fma2(acc[i][3], ap, b1.y);
            }
        }
        __syncthreads();
    }
#pragma unroll
    for (int i = 0; i < 8; i++) {
        int r = m0 + ((i < 4) ? (ty * 4 + i) : (64 + ty * 4 + i - 4));
#pragma unroll
        for (int q = 0; q < 4; q++) {
            int cb = n0 + ((q < 2) ? (tx * 4 + q * 2) : (64 + tx * 4 + (q - 2) * 2));
            float2 v = up2(acc[i][q]);
            g_xproj[(size_t)r * ND3 + cb]     = v.x + bias[cb];
            g_xproj[(size_t)r * ND3 + cb + 1] = v.y + bias[cb + 1];
        }
    }
}

// ---------------------------------------------------------------------------
// Persistent scan: 128 CTAs x 512 threads. CTA c owns columns [8c, 8c+8).
// Warp w: jloc = w>>1, bhalf = w&1; lane owns batch b = 32*bhalf + lane.
// Weights in smem (96KB), h chunks double-buffered, ys stores smem-staged.
// ---------------------------------------------------------------------------
#define WSM_FLOATS   24576              // 3*8*1024
#define HBUF_FLOATS  8448               // 64*132
#define SOUT_FLOATS  576                // 64*9

__global__ void __launch_bounds__(512, 1) scan_kernel(
    const float* __restrict__ hiddens,
    const void*  __restrict__ dones_raw,
    const float* __restrict__ init_carry,
    const float* __restrict__ b_hn,
    float* __restrict__ out)
{
    extern __shared__ __align__(16) float sm[];
    float* wsm  = sm;                                  // 24576
    float* hsb  = sm + WSM_FLOATS;                     // 2*8448
    float* sout = sm + WSM_FLOATS + 2 * HBUF_FLOATS;   // 576
    int*   sdone = (int*)(sout + SOUT_FLOATS);         // 64

    const int tid   = threadIdx.x;
    const int lane  = tid & 31;
    const int w     = tid >> 5;
    const int jloc  = w >> 1;
    const int bhalf = w & 1;
    const int c     = blockIdx.x;
    const int j     = c * 8 + jloc;
    const int bb    = bhalf * 32 + lane;
    float* ys = out + (size_t)BB * DD;

    // one-time weight preload: wsm[(g*8+jl)*1024 + k]
#pragma unroll
    for (int i = 0; i < 12; i++) {
        int e = tid + i * 512;          // float4 id, 0..6143
        int rowloc = e >> 8;            // 0..23
        int kq = e & 255;
        int g = rowloc >> 3, jl = rowloc & 7;
        float4 v = *(const float4*)(g_WhT + (size_t)(g * DD + c * 8 + jl) * DD + kq * 4);
        *(float4*)(wsm + rowloc * 1024 + kq * 4) = v;
    }
    const float* wrp = wsm + jloc * 1024;
    const float* wzp = wsm + (8 + jloc) * 1024;
    const float* wnp = wsm + (16 + jloc) * 1024;
    const float  bhn = b_hn[j];
    const int    is_byte = g_dones_is_byte;
    const int    jc_self = j >> 7, joff_self = j & 127;
    const unsigned char* dones_b = (const unsigned char*)dones_raw;
    const int*           dones_i = (const int*)dones_raw;
    __syncthreads();

    for (int t = 0; t < T_STEPS; t++) {
        if (tid < 64)
            sdone[tid] = is_byte ? (int)dones_b[t * 64 + tid]
                                 : (dones_i[t * 64 + tid] != 0);
        __syncthreads();

        // early (latency-hidden) x-projection loads, coalesced via xprojT
        const size_t tb = (size_t)t * 64 + bb;
        float xr = __ldcg(g_xprojT + (size_t)j * TBTOT + tb);
        float xz = __ldcg(g_xprojT + (size_t)(DD + j) * TBTOT + tb);
        float xn = __ldcg(g_xprojT + (size_t)(2 * DD + j) * TBTOT + tb);

        const float* prevb = (t == 0) ? init_carry : ys + (size_t)(t - 1) * (BB * DD);
        const float* hidt  = hiddens + (size_t)t * (BB * DD);

        // prefetch chunk 0 into regs (done-masked, L2 path)
        float4 pf[4];
#pragma unroll
        for (int i2 = 0; i2 < 4; i2++) {
            int b = (tid >> 5) + 16 * i2;
            const float* src = sdone[b] ? hidt : prevb;
            pf[i2] = __ldcg((const float4*)(src + (size_t)b * DD + lane * 4));
        }

        ull ar0 = 0, ar1 = 0, az0 = 0, az1 = 0, an0 = 0, an1 = 0;
        float hself = 0.f;

        for (int kc = 0; kc < 8; kc++) {
            float* buf = hsb + (kc & 1) * HBUF_FLOATS;
#pragma unroll
            for (int i2 = 0; i2 < 4; i2++) {
                int b = (tid >> 5) + 16 * i2;
                *(float4*)(buf + b * 132 + lane * 4) = pf[i2];
            }
            __syncthreads();
            if (kc < 7) {
                const int k0n = (kc + 1) << 7;
#pragma unroll
                for (int i2 = 0; i2 < 4; i2++) {
                    int b = (tid >> 5) + 16 * i2;
                    const float* src = sdone[b] ? hidt : prevb;
                    pf[i2] = __ldcg((const float4*)(src + (size_t)b * DD + k0n + lane * 4));
                }
            }
            const float* hrow = buf + bb * 132;
            const int k0 = kc << 7;
            if (kc == jc_self) hself = hrow[joff_self];
            const float* wr = wrp + k0;
            const float* wz = wzp + k0;
            const float* wn = wnp + k0;
#pragma unroll 8
            for (int kk = 0; kk < 128; kk += 4) {
                ulonglong2 h2  = *(const ulonglong2*)(hrow + kk);
                ulonglong2 wr2 = *(const ulonglong2*)(wr + kk);
                ulonglong2 wz2 = *(const ulonglong2*)(wz + kk);
                ulonglong2 wn2 = *(const ulonglong2*)(wn + kk);
                fma2(ar0, h2.x, wr2.x); fma2(ar1, h2.y, wr2.y);
                fma2(az0, h2.x, wz2.x); fma2(az1, h2.y, wz2.y);
                fma2(an0, h2.x, wn2.x); fma2(an1, h2.y, wn2.y);
            }
            __syncthreads();
        }

        float2 p;
        p = up2(ar0); float sr = p.x + p.y; p = up2(ar1); sr += p.x + p.y;
        p = up2(az0); float sz = p.x + p.y; p = up2(az1); sz += p.x + p.y;
        p = up2(an0); float sn = p.x + p.y; p = up2(an1); sn += p.x + p.y;

        float r  = sigmoidf_(xr + sr);
        float z  = sigmoidf_(xz + sz);
        float nn = tanhf(xn + r * (sn + bhn));
        float hn = (1.0f - z) * nn + z * hself;

        sout[bb * 9 + jloc] = hn;
        __syncthreads();
        {   // coalesced (32B-run) cooperative stores
            int b = tid >> 3, jl = tid & 7;
            float v = sout[b * 9 + jl];
            ys[((size_t)t * 64 + b) * DD + c * 8 + jl] = v;
            if (t == T_STEPS - 1) out[(size_t)b * DD + c * 8 + jl] = v;
        }
        __syncthreads();
        if (tid == 0) {
            __threadfence();
            atomicAdd(&g_bar, 1u);
            unsigned target = (unsigned)(t + 1) * 128u;
            while (*(volatile unsigned*)&g_bar < target) { }
            __threadfence();
        }
        __syncthreads();
    }
}

// ---------------------------------------------------------------------------
// Launch
// ---------------------------------------------------------------------------
extern "C" void kernel_launch(void* const* d_in, const int* in_sizes, int n_in,
                              void* d_out, int out_size) {
    (void)in_sizes; (void)n_in; (void)out_size;
    const float* ins        = (const float*)d_in[0];
    const float* hiddens    = (const float*)d_in[1];
    const void*  dones      = d_in[2];
    const float* init_carry = (const float*)d_in[3];
    const float* W_i        = (const float*)d_in[4];
    const float* W_h        = (const float*)d_in[5];
    const float* b_i        = (const float*)d_in[6];
    const float* b_hn       = (const float*)d_in[7];
    float* out = (float*)d_out;

    static int smem_set = 0;
    if (!smem_set) {
        cudaFuncSetAttribute(scan_kernel, cudaFuncAttributeMaxDynamicSharedMemorySize,
                             (WSM_FLOATS + 2 * HBUF_FLOATS + SOUT_FLOATS + 64) * 4);
        smem_set = 1;
    }

    probe_dones<<<1, 256>>>((const unsigned*)dones);
    transpose_wh<<<dim3(ND3 / 32, DD / 32), dim3(32, 8)>>>(W_h);
    gemm_xproj<<<dim3(ND3 / 128, TBTOT / 128), 256>>>(ins, W_i, b_i);
    transpose_xproj<<<dim3(ND3 / 32, TBTOT / 32), dim3(32, 8)>>>();
    scan_kernel<<<128, 512, (WSM_FLOATS + 2 * HBUF_FLOATS + SOUT_FLOATS + 64) * 4>>>(
        hiddens, dones, init_carry, b_hn, out);
}

// round 6
// speedup vs baseline: 2.2133x; 1.2599x over previous
#include <cuda_runtime.h>
#include <cstdint>
#include <cstddef>

#define T_STEPS 256
#define BB      64
#define DD      1024
#define ND3     3072
#define TBTOT   (T_STEPS * BB)   // 16384

typedef unsigned long long ull;

// ---------------------------------------------------------------------------
// Device scratch
// ---------------------------------------------------------------------------
__device__ float    g_xproj [(size_t)TBTOT * ND3];   // [tb][n]
__device__ float    g_xprojT[(size_t)ND3 * TBTOT];   // [n][tb]
__device__ float    g_WhT  [(size_t)ND3 * DD];       // [n][k]
__device__ unsigned g_bar;
__device__ int      g_dones_is_byte;

// ---------------------------------------------------------------------------
// f32x2 helpers
// ---------------------------------------------------------------------------
__device__ __forceinline__ ull pk2(float lo, float hi) {
    ull r; asm("mov.b64 %0, {%1, %2};" : "=l"(r) : "f"(lo), "f"(hi)); return r;
}
__device__ __forceinline__ void fma2(ull& d, ull a, ull b) {
    asm("fma.rn.f32x2 %0, %1, %2, %0;" : "+l"(d) : "l"(a), "l"(b));
}
__device__ __forceinline__ float2 up2(ull v) {
    float2 f; asm("mov.b64 {%0, %1}, %2;" : "=f"(f.x), "=f"(f.y) : "l"(v)); return f;
}
__device__ __forceinline__ float sigmoidf_(float x) { return 1.0f / (1.0f + __expf(-x)); }

// cp.async helpers (8-byte copies)
__device__ __forceinline__ void cp_async8(uint32_t dst_smem, const void* src) {
    asm volatile("cp.async.ca.shared.global [%0], [%1], 8;" :: "r"(dst_smem), "l"(src));
}
__device__ __forceinline__ void cp_commit() {
    asm volatile("cp.async.commit_group;");
}
template<int N>
__device__ __forceinline__ void cp_wait() {
    asm volatile("cp.async.wait_group %0;" :: "n"(N));
}

// ---------------------------------------------------------------------------
// probe dones dtype + reset grid barrier
// ---------------------------------------------------------------------------
__global__ void probe_dones(const unsigned* __restrict__ d) {
    __shared__ int any_big;
    if (threadIdx.x == 0) any_big = 0;
    __syncthreads();
    const int nwords = (T_STEPS * BB) / 4;
    int local = 0;
    for (int i = threadIdx.x; i < nwords; i += blockDim.x)
        if (d[i] > 1u) local = 1;
    if (local) any_big = 1;
    __syncthreads();
    if (threadIdx.x == 0) { g_dones_is_byte = any_big; g_bar = 0u; }
}

// ---------------------------------------------------------------------------
// transpose W_h [D,3D] -> g_WhT [3D,D]
// ---------------------------------------------------------------------------
__global__ void transpose_wh(const float* __restrict__ W) {
    __shared__ float tile[32][33];
    int n  = blockIdx.x * 32 + threadIdx.x;
    int k0 = blockIdx.y * 32;
#pragma unroll
    for (int i = threadIdx.y; i < 32; i += 8)
        tile[i][threadIdx.x] = W[(size_t)(k0 + i) * ND3 + n];
    __syncthreads();
    int k  = k0 + threadIdx.x;
    int n0 = blockIdx.x * 32;
#pragma unroll
    for (int i = threadIdx.y; i < 32; i += 8)
        g_WhT[(size_t)(n0 + i) * DD + k] = tile[threadIdx.x][i];
}

// ---------------------------------------------------------------------------
// transpose g_xproj [16384,3072] -> g_xprojT [3072,16384]
// ---------------------------------------------------------------------------
__global__ void transpose_xproj() {
    __shared__ float tile[32][33];
    int n  = blockIdx.x * 32 + threadIdx.x;
    int r0 = blockIdx.y * 32;
#pragma unroll
    for (int i = threadIdx.y; i < 32; i += 8)
        tile[i][threadIdx.x] = g_xproj[(size_t)(r0 + i) * ND3 + n];
    __syncthreads();
    int r  = r0 + threadIdx.x;
    int n0 = blockIdx.x * 32;
#pragma unroll
    for (int i = threadIdx.y; i < 32; i += 8)
        g_xprojT[(size_t)(n0 + i) * TBTOT + r] = tile[threadIdx.x][i];
}

// ---------------------------------------------------------------------------
// x_proj = ins @ W_i + b_i  (unchanged from R4)
// ---------------------------------------------------------------------------
__global__ void __launch_bounds__(256, 2) gemm_xproj(
    const float* __restrict__ A, const float* __restrict__ Bw,
    const float* __restrict__ bias)
{
    __shared__ __align__(16) float As[16][132];
    __shared__ __align__(16) float Bs[16][128];

    const int tid = threadIdx.x;
    const int tx = tid & 15, ty = tid >> 4;
    const int m0 = blockIdx.y << 7, n0 = blockIdx.x << 7;

    ull acc[8][4];
#pragma unroll
    for (int i = 0; i < 8; i++)
#pragma unroll
        for (int q = 0; q < 4; q++) acc[i][q] = 0ull;

    for (int k0 = 0; k0 < DD; k0 += 16) {
#pragma unroll
        for (int i = 0; i < 2; i++) {
            int e = tid + (i << 8);
            int row = e >> 2, c = e & 3;
            float4 v = *(const float4*)(A + (size_t)(m0 + row) * DD + k0 + c * 4);
            As[c * 4 + 0][row] = v.x; As[c * 4 + 1][row] = v.y;
            As[c * 4 + 2][row] = v.z; As[c * 4 + 3][row] = v.w;
        }
#pragma unroll
        for (int i = 0; i < 2; i++) {
            int e = tid + (i << 8);
            int kr = e >> 5, nc = e & 31;
            float4 v = *(const float4*)(Bw + (size_t)(k0 + kr) * ND3 + n0 + nc * 4);
            *(float4*)&Bs[kr][nc * 4] = v;
        }
        __syncthreads();
#pragma unroll
        for (int kk = 0; kk < 16; kk++) {
            float4 a0 = *(const float4*)&As[kk][ty * 4];
            float4 a1 = *(const float4*)&As[kk][64 + ty * 4];
            ulonglong2 b0 = *(const ulonglong2*)&Bs[kk][tx * 4];
            ulonglong2 b1 = *(const ulonglong2*)&Bs[kk][64 + tx * 4];
            float a[8] = {a0.x, a0.y, a0.z, a0.w, a1.x, a1.y, a1.z, a1.w};
#pragma unroll
            for (int i = 0; i < 8; i++) {
                ull ap = pk2(a[i], a[i]);
                fma2(acc[i][0], ap, b0.x); fma2(acc[i][1], ap, b0.y);
                fma2(acc[i][2], ap, b1.x); fma2(acc[i][3], ap, b1.y);
            }
        }
        __syncthreads();
    }
#pragma unroll
    for (int i = 0; i < 8; i++) {
        int r = m0 + ((i < 4) ? (ty * 4 + i) : (64 + ty * 4 + i - 4));
#pragma unroll
        for (int q = 0; q < 4; q++) {
            int cb = n0 + ((q < 2) ? (tx * 4 + q * 2) : (64 + tx * 4 + (q - 2) * 2));
            float2 v = up2(acc[i][q]);
            g_xproj[(size_t)r * ND3 + cb]     = v.x + bias[cb];
            g_xproj[(size_t)r * ND3 + cb + 1] = v.y + bias[cb + 1];
        }
    }
}

// ---------------------------------------------------------------------------
// Persistent scan v2: 128 CTAs x 512 threads, register-tiled, k-pair packed.
//
// CTA c owns j in [8c, 8c+8) -> n-rows {g*1024 + j}. Per step:
//   C[3g x 8j x 64b] = W[24 x 1024] * h[1024 x 64]
// Thread (bgrp, jloc, s):  acc[3 gates][8 b] (ull, halves = k-parity pair),
//   b = bgrp + 8*ii, k-slice s: k = s*4 + 32*q (+128*chunk), quads of 4 k.
// h chunks (128 k) staged [b][130] via cp.async double-buffer.
// Reduce threads (rb, rjl=s) do 8-way k-slice sum + gate math; h carried in reg.
// ---------------------------------------------------------------------------
#define W_OFF    0
#define W_STRIDE 1032
#define HST_OFF  24768            // 24*1032
#define HST_BUF  8320             // 64*130
#define PART_OFF 41408            // HST_OFF + 2*8320
#define PART_STRIDE 66
#define SOUT_OFF 54080            // PART_OFF + 192*66
#define DONE_OFF 54656            // SOUT_OFF + 576
#define SMEM_FLOATS 54720

__global__ void __launch_bounds__(512, 1) scan_kernel(
    const float* __restrict__ hiddens,
    const void*  __restrict__ dones_raw,
    const float* __restrict__ init_carry,
    const float* __restrict__ b_hn,
    float* __restrict__ out)
{
    extern __shared__ __align__(16) float sm[];
    float* wsm  = sm + W_OFF;
    float* hst  = sm + HST_OFF;
    float* part = sm + PART_OFF;
    float* sout = sm + SOUT_OFF;
    int*   sdone = (int*)(sm + DONE_OFF);

    const int tid  = threadIdx.x;
    const int c    = blockIdx.x;
    // compute role
    const int bgrp = tid & 7;
    const int jloc = (tid >> 3) & 7;
    const int s    = tid >> 6;          // k-slice 0..7
    // staging role
    const int sb   = tid >> 3;          // 0..63
    const int skq  = tid & 7;
    // reduce role
    const int rb   = tid & 63;
    const int rjl  = tid >> 6;          // 0..7
    const int jr   = c * 8 + rjl;

    float* ys = out + (size_t)BB * DD;

    // one-time weight load: wsm[(g*8+jl)*1032 + k]
#pragma unroll
    for (int i = 0; i < 12; i++) {
        int e = tid + i * 512;          // float4 id 0..6143
        int row = e >> 8;               // 0..23
        int kq  = e & 255;
        int g = row >> 3, jl = row & 7;
        float4 v = *(const float4*)(g_WhT + (size_t)(g * DD + c * 8 + jl) * DD + kq * 4);
        *(float4*)(wsm + row * W_STRIDE + kq * 4) = v;
    }

    const float* w0p = wsm + (0 * 8 + jloc) * W_STRIDE;
    const float* w1p = wsm + (1 * 8 + jloc) * W_STRIDE;
    const float* w2p = wsm + (2 * 8 + jloc) * W_STRIDE;

    float hprev = init_carry[(size_t)rb * DD + jr];
    const float bhn_r = b_hn[jr];
    const int is_byte = g_dones_is_byte;
    const unsigned char* dones_b = (const unsigned char*)dones_raw;
    const int*           dones_i = (const int*)dones_raw;

    const uint32_t hst_base_u32 = (uint32_t)__cvta_generic_to_shared(hst);
    const uint32_t my_dst_off   = (uint32_t)((sb * 130 + skq * 2) * 4);

    __syncthreads();

    for (int t = 0; t < T_STEPS; t++) {
        if (tid < 64)
            sdone[tid] = is_byte ? (int)dones_b[t * 64 + tid]
                                 : (dones_i[t * 64 + tid] != 0);
        __syncthreads();

        // reduce-role prefetches (latency hidden under the 8-chunk compute)
        const size_t tb = (size_t)t * 64 + rb;
        float xr = __ldcg(g_xprojT + (size_t)jr * TBTOT + tb);
        float xz = __ldcg(g_xprojT + (size_t)(DD + jr) * TBTOT + tb);
        float xn = __ldcg(g_xprojT + (size_t)(2 * DD + jr) * TBTOT + tb);
        float hcand = __ldcg(hiddens + (size_t)t * (BB * DD) + (size_t)rb * DD + jr);
        const int mydone = sdone[rb];

        const float* prevb = (t == 0) ? init_carry : ys + (size_t)(t - 1) * (BB * DD);
        const float* hidt  = hiddens + (size_t)t * (BB * DD);
        const float* srcrow = (sdone[sb] ? hidt : prevb) + (size_t)sb * DD;

        // stage chunk 0
        {
            uint32_t dst = hst_base_u32 + my_dst_off;
#pragma unroll
            for (int i = 0; i < 8; i++)
                cp_async8(dst + i * 64, srcrow + skq * 2 + 16 * i);
            cp_commit();
        }

        ull acc[3][8];
#pragma unroll
        for (int g = 0; g < 3; g++)
#pragma unroll
            for (int ii = 0; ii < 8; ii++) acc[g][ii] = 0ull;

        for (int chunk = 0; chunk < 8; chunk++) {
            __syncthreads();   // buf (chunk+1)&1 free (compute of chunk-1 done)
            if (chunk < 7) {
                const int kb = (chunk + 1) << 7;
                uint32_t dst = hst_base_u32 + (uint32_t)(((chunk + 1) & 1) * HST_BUF * 4) + my_dst_off;
#pragma unroll
                for (int i = 0; i < 8; i++)
                    cp_async8(dst + i * 64, srcrow + kb + skq * 2 + 16 * i);
                cp_commit();
                cp_wait<1>();
            } else {
                cp_wait<0>();
            }
            __syncthreads();   // staged chunk visible to all

            const float* buf = hst + (chunk & 1) * HST_BUF;
            const int kw = chunk << 7;
#pragma unroll
            for (int q = 0; q < 4; q++) {
                const int k0 = s * 4 + q * 32;
                ulonglong2 wr2 = *(const ulonglong2*)(w0p + kw + k0);
                ulonglong2 wz2 = *(const ulonglong2*)(w1p + kw + k0);
                ulonglong2 wn2 = *(const ulonglong2*)(w2p + kw + k0);
#pragma unroll
                for (int ii = 0; ii < 8; ii++) {
                    const float* hb = buf + (bgrp + 8 * ii) * 130 + k0;
                    ull h01 = *(const ull*)(hb);
                    ull h23 = *(const ull*)(hb + 2);
                    fma2(acc[0][ii], h01, wr2.x); fma2(acc[0][ii], h23, wr2.y);
                    fma2(acc[1][ii], h01, wz2.x); fma2(acc[1][ii], h23, wz2.y);
                    fma2(acc[2][ii], h01, wn2.x); fma2(acc[2][ii], h23, wn2.y);
                }
            }
        }

        // write partials (fold k-parity halves)
#pragma unroll
        for (int g = 0; g < 3; g++)
#pragma unroll
            for (int ii = 0; ii < 8; ii++) {
                float2 p = up2(acc[g][ii]);
                part[((s * 3 + g) * 8 + jloc) * PART_STRIDE + (bgrp + 8 * ii)] = p.x + p.y;
            }
        __syncthreads();

        // 8-way k-slice reduce + gates (thread (rb, rjl))
        float sr = 0.f, szv = 0.f, snv = 0.f;
#pragma unroll
        for (int ss = 0; ss < 8; ss++) {
            sr  += part[((ss * 3 + 0) * 8 + rjl) * PART_STRIDE + rb];
            szv += part[((ss * 3 + 1) * 8 + rjl) * PART_STRIDE + rb];
            snv += part[((ss * 3 + 2) * 8 + rjl) * PART_STRIDE + rb];
        }
        float hself = mydone ? hcand : hprev;
        float r  = sigmoidf_(xr + sr);
        float z  = sigmoidf_(xz + szv);
        float nn = tanhf(xn + r * (snv + bhn_r));
        float hn = (1.0f - z) * nn + z * hself;
        hprev = hn;

        sout[rb * 9 + rjl] = hn;
        __syncthreads();
        {   // coalesced cooperative store
            int b = tid >> 3, jl = tid & 7;
            float v = sout[b * 9 + jl];
            ys[((size_t)t * 64 + b) * DD + c * 8 + jl] = v;
            if (t == T_STEPS - 1) out[(size_t)b * DD + c * 8 + jl] = v;
        }
        __syncthreads();
        if (tid == 0) {
            __threadfence();
            atomicAdd(&g_bar, 1u);
            unsigned target = (unsigned)(t + 1) * 128u;
            while (*(volatile unsigned*)&g_bar < target) { }
            __threadfence();
        }
        __syncthreads();
    }
}

// ---------------------------------------------------------------------------
// Launch
// ---------------------------------------------------------------------------
extern "C" void kernel_launch(void* const* d_in, const int* in_sizes, int n_in,
                              void* d_out, int out_size) {
    (void)in_sizes; (void)n_in; (void)out_size;
    const float* ins        = (const float*)d_in[0];
    const float* hiddens    = (const float*)d_in[1];
    const void*  dones      = d_in[2];
    const float* init_carry = (const float*)d_in[3];
    const float* W_i        = (const float*)d_in[4];
    const float* W_h        = (const float*)d_in[5];
    const float* b_i        = (const float*)d_in[6];
    const float* b_hn       = (const float*)d_in[7];
    float* out = (float*)d_out;

    static int smem_set = 0;
    if (!smem_set) {
        cudaFuncSetAttribute(scan_kernel, cudaFuncAttributeMaxDynamicSharedMemorySize,
                             SMEM_FLOATS * 4);
        smem_set = 1;
    }

    probe_dones<<<1, 256>>>((const unsigned*)dones);
    transpose_wh<<<dim3(ND3 / 32, DD / 32), dim3(32, 8)>>>(W_h);
    gemm_xproj<<<dim3(ND3 / 128, TBTOT / 128), 256>>>(ins, W_i, b_i);
    transpose_xproj<<<dim3(ND3 / 32, TBTOT / 32), dim3(32, 8)>>>();
    scan_kernel<<<128, 512, SMEM_FLOATS * 4>>>(hiddens, dones, init_carry, b_hn, out);
}

// round 9
// speedup vs baseline: 2.4211x; 1.0939x over previous
#include <cuda_runtime.h>
#include <cuda_bf16.h>
#include <cstdint>
#include <cstddef>

#define T_STEPS 256
#define BB      64
#define DD      1024
#define ND3     3072
#define TBTOT   (T_STEPS * BB)   // 16384

typedef unsigned long long ull;

// ---------------------------------------------------------------------------
// Device scratch
// ---------------------------------------------------------------------------
__device__ float          g_xprojT[(size_t)ND3 * TBTOT];   // [n][tb]
__device__ float          g_WhT  [(size_t)ND3 * DD];       // [n][k]
__device__ __nv_bfloat16  g_Ahi[(size_t)TBTOT * DD];       // ins split  [m][k]
__device__ __nv_bfloat16  g_Alo[(size_t)TBTOT * DD];
__device__ __nv_bfloat16  g_Bhi[(size_t)ND3 * DD];         // W_i^T split [n][k]
__device__ __nv_bfloat16  g_Blo[(size_t)ND3 * DD];
__device__ unsigned g_bar;
__device__ int      g_dones_is_byte;

// ---------------------------------------------------------------------------
// f32x2 helpers (scan)
// ---------------------------------------------------------------------------
__device__ __forceinline__ void fma2(ull& d, ull a, ull b) {
    asm("fma.rn.f32x2 %0, %1, %2, %0;" : "+l"(d) : "l"(a), "l"(b));
}
__device__ __forceinline__ float2 up2(ull v) {
    float2 f; asm("mov.b64 {%0, %1}, %2;" : "=f"(f.x), "=f"(f.y) : "l"(v)); return f;
}
__device__ __forceinline__ float sigmoidf_(float x) { return 1.0f / (1.0f + __expf(-x)); }

// cp.async helpers
__device__ __forceinline__ void cp_async8(uint32_t dst_smem, const void* src) {
    asm volatile("cp.async.ca.shared.global [%0], [%1], 8;" :: "r"(dst_smem), "l"(src));
}
__device__ __forceinline__ void cp_async16(uint32_t dst_smem, const void* src) {
    asm volatile("cp.async.cg.shared.global [%0], [%1], 16;" :: "r"(dst_smem), "l"(src));
}
__device__ __forceinline__ void cp_commit() { asm volatile("cp.async.commit_group;"); }
template<int N>
__device__ __forceinline__ void cp_wait() {
    asm volatile("cp.async.wait_group %0;" :: "n"(N));
}

// ---------------------------------------------------------------------------
// mma.sync helpers (portable PTX: sm_80+, works under compute_103)
// ---------------------------------------------------------------------------
__device__ __forceinline__ void ldsm4(uint32_t* f, uint32_t addr) {
    asm volatile("ldmatrix.sync.aligned.m8n8.x4.shared.b16 {%0,%1,%2,%3}, [%4];"
        : "=r"(f[0]), "=r"(f[1]), "=r"(f[2]), "=r"(f[3]) : "r"(addr));
}
__device__ __forceinline__ void mma16816(float* c, const uint32_t* a, const uint32_t* b) {
    asm volatile("mma.sync.aligned.m16n8k16.row.col.f32.bf16.bf16.f32 "
        "{%0,%1,%2,%3}, {%4,%5,%6,%7}, {%8,%9}, {%0,%1,%2,%3};"
        : "+f"(c[0]), "+f"(c[1]), "+f"(c[2]), "+f"(c[3])
        : "r"(a[0]), "r"(a[1]), "r"(a[2]), "r"(a[3]), "r"(b[0]), "r"(b[1]));
}

// ---------------------------------------------------------------------------
// probe dones dtype + reset grid barrier
// ---------------------------------------------------------------------------
__global__ void probe_dones(const unsigned* __restrict__ d) {
    __shared__ int any_big;
    if (threadIdx.x == 0) any_big = 0;
    __syncthreads();
    const int nwords = (T_STEPS * BB) / 4;
    int local = 0;
    for (int i = threadIdx.x; i < nwords; i += blockDim.x)
        if (d[i] > 1u) local = 1;
    if (local) any_big = 1;
    __syncthreads();
    if (threadIdx.x == 0) { g_dones_is_byte = any_big; g_bar = 0u; }
}

// ---------------------------------------------------------------------------
// transpose W_h [D,3D] -> g_WhT [3D,D]
// ---------------------------------------------------------------------------
__global__ void transpose_wh(const float* __restrict__ W) {
    __shared__ float tile[32][33];
    int n  = blockIdx.x * 32 + threadIdx.x;
    int k0 = blockIdx.y * 32;
#pragma unroll
    for (int i = threadIdx.y; i < 32; i += 8)
        tile[i][threadIdx.x] = W[(size_t)(k0 + i) * ND3 + n];
    __syncthreads();
    int k  = k0 + threadIdx.x;
    int n0 = blockIdx.x * 32;
#pragma unroll
    for (int i = threadIdx.y; i < 32; i += 8)
        g_WhT[(size_t)(n0 + i) * DD + k] = tile[threadIdx.x][i];
}

// ---------------------------------------------------------------------------
// split ins -> bf16 hi/lo [m][k]
// ---------------------------------------------------------------------------
__global__ void convert_A(const float* __restrict__ A) {
    size_t i = ((size_t)blockIdx.x * 256 + threadIdx.x) * 4;
    float4 v = *(const float4*)(A + i);
    __nv_bfloat16 h[4], l[4];
    float f[4] = {v.x, v.y, v.z, v.w};
#pragma unroll
    for (int q = 0; q < 4; q++) {
        h[q] = __float2bfloat16(f[q]);
        l[q] = __float2bfloat16(f[q] - __bfloat162float(h[q]));
    }
    *(ull*)(g_Ahi + i) = *(ull*)h;
    *(ull*)(g_Alo + i) = *(ull*)l;
}

// ---------------------------------------------------------------------------
// W_i [k][3D] -> g_Bhi/g_Blo [n][k] bf16 (transpose + split)
// ---------------------------------------------------------------------------
__global__ void convert_wi(const float* __restrict__ W) {
    __shared__ float tile[32][33];
    int n  = blockIdx.x * 32 + threadIdx.x;
    int k0 = blockIdx.y * 32;
#pragma unroll
    for (int i = threadIdx.y; i < 32; i += 8)
        tile[i][threadIdx.x] = W[(size_t)(k0 + i) * ND3 + n];
    __syncthreads();
    int k  = k0 + threadIdx.x;
    int n0 = blockIdx.x * 32;
#pragma unroll
    for (int i = threadIdx.y; i < 32; i += 8) {
        float x = tile[threadIdx.x][i];
        __nv_bfloat16 hi = __float2bfloat16(x);
        __nv_bfloat16 lo = __float2bfloat16(x - __bfloat162float(hi));
        g_Bhi[(size_t)(n0 + i) * DD + k] = hi;
        g_Blo[(size_t)(n0 + i) * DD + k] = lo;
    }
}

// ---------------------------------------------------------------------------
// HMMA bf16-split GEMM, epilogue writes TRANSPOSED + bias:
//   g_xprojT[n][m] = (ins @ W_i)[m][n] + b_i[n]
// Tile 128x128, 256 thr (8 warps, warp tile 32m x 64n), K-chunk 32, dbl-buffer.
// smem per buffer set: Ahi|Alo|Bhi|Blo, each [128 rows][40 bf16] (80B stride).
// ---------------------------------------------------------------------------
#define GM_ARR_B   10240                   // 128*80
#define GM_SET_B   (4 * GM_ARR_B)          // 40960
#define GM_DYN_B   (2 * GM_SET_B)          // 81920 (epilogue Cs 128*132*4=67584 reuses)

__global__ void __launch_bounds__(256) gemm_xproj_mma(const float* __restrict__ bias)
{
    extern __shared__ __align__(16) unsigned char dynsm[];
    const uint32_t sb = (uint32_t)__cvta_generic_to_shared(dynsm);

    const int tid  = threadIdx.x;
    const int lane = tid & 31;
    const int warp = tid >> 5;
    const int wm   = warp & 3;            // 4 m-warps
    const int wn   = warp >> 2;           // 2 n-warps
    const int n0   = blockIdx.x << 7;
    const int m0   = blockIdx.y << 7;

    float c[2][8][4];
#pragma unroll
    for (int mt = 0; mt < 2; mt++)
#pragma unroll
        for (int j = 0; j < 8; j++)
#pragma unroll
            for (int q = 0; q < 4; q++) c[mt][j][q] = 0.f;

    // stage chunk kc into buffer set (kc&1): 2048 x 16B via cp.async
    auto stage = [&](int kc) {
        const int kb = kc * 32;
        const uint32_t bo = sb + (kc & 1) * GM_SET_B;
#pragma unroll
        for (int i = 0; i < 8; i++) {
            int e = tid + (i << 8);
            int arr = e >> 9;
            int row = (e >> 2) & 127;
            int seg = e & 3;
            const __nv_bfloat16* gsrc;
            if      (arr == 0) gsrc = g_Ahi + (size_t)(m0 + row) * DD;
            else if (arr == 1) gsrc = g_Alo + (size_t)(m0 + row) * DD;
            else if (arr == 2) gsrc = g_Bhi + (size_t)(n0 + row) * DD;
            else               gsrc = g_Blo + (size_t)(n0 + row) * DD;
            cp_async16(bo + arr * GM_ARR_B + row * 80 + seg * 16, gsrc + kb + seg * 8);
        }
        cp_commit();
    };

    stage(0);
    for (int kc = 0; kc < 32; kc++) {
        if (kc < 31) { stage(kc + 1); cp_wait<1>(); }
        else         { cp_wait<0>(); }
        __syncthreads();

        const uint32_t cur  = sb + (kc & 1) * GM_SET_B;
        const uint32_t aoffh = cur;
        const uint32_t aoffl = cur + GM_ARR_B;
        const uint32_t boffh = cur + 2 * GM_ARR_B;
        const uint32_t boffl = cur + 3 * GM_ARR_B;

#pragma unroll
        for (int ks = 0; ks < 2; ks++) {
            uint32_t ahi[2][4], alo[2][4];
#pragma unroll
            for (int mt = 0; mt < 2; mt++) {
                uint32_t rowb = (uint32_t)((wm * 32 + mt * 16 + (lane & 15)) * 80
                                           + ks * 32 + (lane >> 4) * 16);
                ldsm4(ahi[mt], aoffh + rowb);
                ldsm4(alo[mt], aoffl + rowb);
            }
#pragma unroll
            for (int g = 0; g < 4; g++) {
                uint32_t nrow = (uint32_t)(wn * 64 + g * 16 +
                                 ((lane & 7) | (((lane >> 4) & 1) << 3)));
                uint32_t rb = nrow * 80 + ks * 32 + ((lane >> 3) & 1) * 16;
                uint32_t bhi[4], blo[4];
                ldsm4(bhi, boffh + rb);
                ldsm4(blo, boffl + rb);
#pragma unroll
                for (int mt = 0; mt < 2; mt++) {
                    mma16816(c[mt][g * 2],     ahi[mt], bhi);
                    mma16816(c[mt][g * 2],     ahi[mt], blo);
                    mma16816(c[mt][g * 2],     alo[mt], bhi);
                    mma16816(c[mt][g * 2 + 1], ahi[mt], bhi + 2);
                    mma16816(c[mt][g * 2 + 1], ahi[mt], blo + 2);
                    mma16816(c[mt][g * 2 + 1], alo[mt], bhi + 2);
                }
            }
        }
        __syncthreads();   // protect buffer being re-staged next iteration
    }

    // epilogue: stage C transposed in smem Cs[n][m] (stride 132), then store
    float* Cs = (float*)dynsm;
#pragma unroll
    for (int mt = 0; mt < 2; mt++)
#pragma unroll
        for (int j = 0; j < 8; j++)
#pragma unroll
            for (int q = 0; q < 4; q++) {
                int mrow = wm * 32 + mt * 16 + (lane >> 2) + ((q >> 1) & 1) * 8;
                int ncol = wn * 64 + j * 8 + (lane & 3) * 2 + (q & 1);
                Cs[ncol * 132 + mrow] = c[mt][j][q];
            }
    __syncthreads();

    {
        int n  = tid >> 1;
        int mh = (tid & 1) * 64;
        float bv = __ldg(&bias[n0 + n]);
        float* dst = g_xprojT + (size_t)(n0 + n) * TBTOT + m0 + mh;
        const float* src = Cs + n * 132 + mh;
#pragma unroll
        for (int i = 0; i < 16; i++) {
            float4 v = *(const float4*)(src + i * 4);
            v.x += bv; v.y += bv; v.z += bv; v.w += bv;
            *(float4*)(dst + i * 4) = v;
        }
    }
}

// ---------------------------------------------------------------------------
// Persistent scan (unchanged, proven): 128 CTAs x 512 threads
// ---------------------------------------------------------------------------
#define W_OFF    0
#define W_STRIDE 1032
#define HST_OFF  24768
#define HST_BUF  8320
#define PART_OFF 41408
#define PART_STRIDE 66
#define SOUT_OFF 54080
#define DONE_OFF 54656
#define SMEM_FLOATS 54720

__global__ void __launch_bounds__(512, 1) scan_kernel(
    const float* __restrict__ hiddens,
    const void*  __restrict__ dones_raw,
    const float* __restrict__ init_carry,
    const float* __restrict__ b_hn,
    float* __restrict__ out)
{
    extern __shared__ __align__(16) float sm[];
    float* wsm  = sm + W_OFF;
    float* hst  = sm + HST_OFF;
    float* part = sm + PART_OFF;
    float* sout = sm + SOUT_OFF;
    int*   sdone = (int*)(sm + DONE_OFF);

    const int tid  = threadIdx.x;
    const int c    = blockIdx.x;
    const int bgrp = tid & 7;
    const int jloc = (tid >> 3) & 7;
    const int s    = tid >> 6;
    const int sb   = tid >> 3;
    const int skq  = tid & 7;
    const int rb   = tid & 63;
    const int rjl  = tid >> 6;
    const int jr   = c * 8 + rjl;

    float* ys = out + (size_t)BB * DD;

#pragma unroll
    for (int i = 0; i < 12; i++) {
        int e = tid + i * 512;
        int row = e >> 8;
        int kq  = e & 255;
        int g = row >> 3, jl = row & 7;
        float4 v = *(const float4*)(g_WhT + (size_t)(g * DD + c * 8 + jl) * DD + kq * 4);
        *(float4*)(wsm + row * W_STRIDE + kq * 4) = v;
    }

    const float* w0p = wsm + (0 * 8 + jloc) * W_STRIDE;
    const float* w1p = wsm + (1 * 8 + jloc) * W_STRIDE;
    const float* w2p = wsm + (2 * 8 + jloc) * W_STRIDE;

    float hprev = init_carry[(size_t)rb * DD + jr];
    const float bhn_r = b_hn[jr];
    const int is_byte = g_dones_is_byte;
    const unsigned char* dones_b = (const unsigned char*)dones_raw;
    const int*           dones_i = (const int*)dones_raw;

    const uint32_t hst_base_u32 = (uint32_t)__cvta_generic_to_shared(hst);
    const uint32_t my_dst_off   = (uint32_t)((sb * 130 + skq * 2) * 4);

    __syncthreads();

    for (int t = 0; t < T_STEPS; t++) {
        if (tid < 64)
            sdone[tid] = is_byte ? (int)dones_b[t * 64 + tid]
                                 : (dones_i[t * 64 + tid] != 0);
        __syncthreads();

        const size_t tb = (size_t)t * 64 + rb;
        float xr = __ldcg(g_xprojT + (size_t)jr * TBTOT + tb);
        float xz = __ldcg(g_xprojT + (size_t)(DD + jr) * TBTOT + tb);
        float xn = __ldcg(g_xprojT + (size_t)(2 * DD + jr) * TBTOT + tb);
        float hcand = __ldcg(hiddens + (size_t)t * (BB * DD) + (size_t)rb * DD + jr);
        const int mydone = sdone[rb];

        const float* prevb = (t == 0) ? init_carry : ys + (size_t)(t - 1) * (BB * DD);
        const float* hidt  = hiddens + (size_t)t * (BB * DD);
        const float* srcrow = (sdone[sb] ? hidt : prevb) + (size_t)sb * DD;

        {
            uint32_t dst = hst_base_u32 + my_dst_off;
#pragma unroll
            for (int i = 0; i < 8; i++)
                cp_async8(dst + i * 64, srcrow + skq * 2 + 16 * i);
            cp_commit();
        }

        ull acc[3][8];
#pragma unroll
        for (int g = 0; g < 3; g++)
#pragma unroll
            for (int ii = 0; ii < 8; ii++) acc[g][ii] = 0ull;

        for (int chunk = 0; chunk < 8; chunk++) {
            __syncthreads();
            if (chunk < 7) {
                const int kb = (chunk + 1) << 7;
                uint32_t dst = hst_base_u32 + (uint32_t)(((chunk + 1) & 1) * HST_BUF * 4) + my_dst_off;
#pragma unroll
                for (int i = 0; i < 8; i++)
                    cp_async8(dst + i * 64, srcrow + kb + skq * 2 + 16 * i);
                cp_commit();
                cp_wait<1>();
            } else {
                cp_wait<0>();
            }
            __syncthreads();

            const float* buf = hst + (chunk & 1) * HST_BUF;
            const int kw = chunk << 7;
#pragma unroll
            for (int q = 0; q < 4; q++) {
                const int k0 = s * 4 + q * 32;
                ulonglong2 wr2 = *(const ulonglong2*)(w0p + kw + k0);
                ulonglong2 wz2 = *(const ulonglong2*)(w1p + kw + k0);
                ulonglong2 wn2 = *(const ulonglong2*)(w2p + kw + k0);
#pragma unroll
                for (int ii = 0; ii < 8; ii++) {
                    const float* hb = buf + (bgrp + 8 * ii) * 130 + k0;
                    ull h01 = *(const ull*)(hb);
                    ull h23 = *(const ull*)(hb + 2);
                    fma2(acc[0][ii], h01, wr2.x); fma2(acc[0][ii], h23, wr2.y);
                    fma2(acc[1][ii], h01, wz2.x); fma2(acc[1][ii], h23, wz2.y);
                    fma2(acc[2][ii], h01, wn2.x); fma2(acc[2][ii], h23, wn2.y);
                }
            }
        }

#pragma unroll
        for (int g = 0; g < 3; g++)
#pragma unroll
            for (int ii = 0; ii < 8; ii++) {
                float2 p = up2(acc[g][ii]);
                part[((s * 3 + g) * 8 + jloc) * PART_STRIDE + (bgrp + 8 * ii)] = p.x + p.y;
            }
        __syncthreads();

        float sr = 0.f, szv = 0.f, snv = 0.f;
#pragma unroll
        for (int ss = 0; ss < 8; ss++) {
            sr  += part[((ss * 3 + 0) * 8 + rjl) * PART_STRIDE + rb];
            szv += part[((ss * 3 + 1) * 8 + rjl) * PART_STRIDE + rb];
            snv += part[((ss * 3 + 2) * 8 + rjl) * PART_STRIDE + rb];
        }
        float hself = mydone ? hcand : hprev;
        float r  = sigmoidf_(xr + sr);
        float z  = sigmoidf_(xz + szv);
        float nn = tanhf(xn + r * (snv + bhn_r));
        float hn = (1.0f - z) * nn + z * hself;
        hprev = hn;

        sout[rb * 9 + rjl] = hn;
        __syncthreads();
        {
            int b = tid >> 3, jl = tid & 7;
            float v = sout[b * 9 + jl];
            ys[((size_t)t * 64 + b) * DD + c * 8 + jl] = v;
            if (t == T_STEPS - 1) out[(size_t)b * DD + c * 8 + jl] = v;
        }
        __syncthreads();
        if (tid == 0) {
            __threadfence();
            atomicAdd(&g_bar, 1u);
            unsigned target = (unsigned)(t + 1) * 128u;
            while (*(volatile unsigned*)&g_bar < target) { }
            __threadfence();
        }
        __syncthreads();
    }
}

// ---------------------------------------------------------------------------
// Launch
// ---------------------------------------------------------------------------
extern "C" void kernel_launch(void* const* d_in, const int* in_sizes, int n_in,
                              void* d_out, int out_size) {
    (void)in_sizes; (void)n_in; (void)out_size;
    const float* ins        = (const float*)d_in[0];
    const float* hiddens    = (const float*)d_in[1];
    const void*  dones      = d_in[2];
    const float* init_carry = (const float*)d_in[3];
    const float* W_i        = (const float*)d_in[4];
    const float* W_h        = (const float*)d_in[5];
    const float* b_i        = (const float*)d_in[6];
    const float* b_hn       = (const float*)d_in[7];
    float* out = (float*)d_out;

    static int attr_set = 0;
    if (!attr_set) {
        cudaFuncSetAttribute(scan_kernel, cudaFuncAttributeMaxDynamicSharedMemorySize,
                             SMEM_FLOATS * 4);
        cudaFuncSetAttribute(gemm_xproj_mma, cudaFuncAttributeMaxDynamicSharedMemorySize,
                             GM_DYN_B);
        attr_set = 1;
    }

    probe_dones<<<1, 256>>>((const unsigned*)dones);
    transpose_wh<<<dim3(ND3 / 32, DD / 32), dim3(32, 8)>>>(W_h);
    convert_A<<<(TBTOT * DD) / (256 * 4), 256>>>(ins);
    convert_wi<<<dim3(ND3 / 32, DD / 32), dim3(32, 8)>>>(W_i);
    gemm_xproj_mma<<<dim3(ND3 / 128, TBTOT / 128), 256, GM_DYN_B>>>(b_i);
    scan_kernel<<<128, 512, SMEM_FLOATS * 4>>>(hiddens, dones, init_carry, b_hn, out);
}